// round 7
// baseline (speedup 1.0000x reference)
#include <cuda_runtime.h>

#define DEVINL __device__ __forceinline__
typedef unsigned long long ull;

constexpr int B = 64, T = 256, W = 20, NP = 6, NT = 12, CC = 32, FD = 8, PROJ = 64;
constexpr int NG = 4 * PROJ;            // 256 gates
constexpr int NWIN = B * T;             // 16384

// scratch
__device__ float g_xg[NWIN * NG];       // 16 MB: xg = feat @ Wih^T + (bih+bhh)
__device__ float g_hs[NWIN * PROJ];     // 4 MB: per-step hidden states

DEVINL void fma2(ull& d, ull a, ull b) {
    asm("fma.rn.f32x2 %0, %1, %2, %0;" : "+l"(d) : "l"(a), "l"(b));
}
DEVINL void add2(ull& d, ull a, ull b) {
    asm("add.rn.f32x2 %0, %1, %2;" : "=l"(d) : "l"(a), "l"(b));
}
DEVINL float hsum2(ull a) {
    float lo, hi;
    asm("mov.b64 {%0,%1}, %2;" : "=f"(lo), "=f"(hi) : "l"(a));
    return lo + hi;
}
DEVINL ull pack2(float lo, float hi) {
    ull r;
    asm("mov.b64 %0, {%1,%2};" : "=l"(r) : "f"(lo), "f"(hi));
    return r;
}

DEVINL float sigm(float x) { return __fdividef(1.f, 1.f + __expf(-x)); }
DEVINL float tanh_(float x) { return __fdividef(2.f, 1.f + __expf(-2.f * x)) - 1.f; }

// ---------------------------------------------------------------------------
// smem layout (floats) — dynamic shared
//   conv1p weights: channel-PAIRS  [(3m+k)*64 + 2o]
//   conv1t / conv2 weights: channel-QUADS [(3mm+k)*128 + 4o]
// ---------------------------------------------------------------------------
constexpr int OFF_W1P  = 0;                       // 576
constexpr int OFF_W1T  = OFF_W1P + 576;           // 1152
constexpr int OFF_W2P  = OFF_W1T + 1152;          // 3072
constexpr int OFF_W2T  = OFF_W2P + 3072;          // 3072
constexpr int OFF_B1P  = OFF_W2T + 3072;          // 32
constexpr int OFF_B1T  = OFF_B1P + 32;            // 32
constexpr int OFF_B2P  = OFF_B1T + 32;            // 32
constexpr int OFF_B2T  = OFF_B2P + 32;            // 32
constexpr int OFF_BIAS = OFF_B2T + 32;            // 256
constexpr int OFF_XP   = OFF_BIAS + 256;          // 8 * 128
constexpr int OFF_XT   = OFF_XP + 8 * 128;        // 8 * 256
constexpr int OFF_H1   = OFF_XT + 8 * 256;        // 8 * 576
constexpr int OFF_CAT  = OFF_H1 + 8 * 576;        // 8 * 80
constexpr int OFF_PRJ  = OFF_CAT + 8 * 80;        // 8 * 64
constexpr int SMEM_FLOATS = OFF_PRJ + 8 * 64;
constexpr int SMEM_BYTES = SMEM_FLOATS * 4;

// ---------------------------------------------------------------------------
// conv1 half-pass over channel PAIRS (pressure): 9 outputs j = J0..J0+8.
// ---------------------------------------------------------------------------
template <int NPAIR, int STRIDE, int J0>
DEVINL void conv1P_half(const float* __restrict__ s_x, const float* __restrict__ s_w,
                        float bv, float* __restrict__ h1T) {
    ull acc[9];
#pragma unroll
    for (int j = 0; j < 9; j++) acc[j] = 0ull;
#pragma unroll
    for (int m = 0; m < NPAIR; m++) {
        ull w0 = *reinterpret_cast<const ull*>(s_w + (3 * m + 0) * 64);
        ull w1 = *reinterpret_cast<const ull*>(s_w + (3 * m + 1) * 64);
        ull w2 = *reinterpret_cast<const ull*>(s_w + (3 * m + 2) * 64);
#pragma unroll
        for (int rr = 0; rr < 11; rr++) {
            ull v = *reinterpret_cast<const ull*>(s_x + (J0 + rr) * STRIDE + 2 * m);
            if (rr < 9) fma2(acc[rr], v, w0);
            if (rr >= 1 && rr <= 9) fma2(acc[rr - 1], v, w1);
            if (rr >= 2) fma2(acc[rr - 2], v, w2);
        }
    }
#pragma unroll
    for (int j = 0; j < 9; j++)
        h1T[(J0 + j) * 32] = fmaxf(hsum2(acc[j]) + bv, 0.f);
}

// ---------------------------------------------------------------------------
// conv1 half-pass over channel QUADS (torque): 9 outputs j = J0..J0+8.
// ---------------------------------------------------------------------------
template <int NQUAD, int STRIDE, int J0>
DEVINL void conv1Q_half(const float* __restrict__ s_x, const float* __restrict__ s_w,
                        float bv, float* __restrict__ h1T) {
    ull acc[9];
#pragma unroll
    for (int j = 0; j < 9; j++) acc[j] = 0ull;
#pragma unroll
    for (int mm = 0; mm < NQUAD; mm++) {
        ulonglong2 w0 = *reinterpret_cast<const ulonglong2*>(s_w + (3 * mm + 0) * 128);
        ulonglong2 w1 = *reinterpret_cast<const ulonglong2*>(s_w + (3 * mm + 1) * 128);
        ulonglong2 w2 = *reinterpret_cast<const ulonglong2*>(s_w + (3 * mm + 2) * 128);
#pragma unroll
        for (int rr = 0; rr < 11; rr++) {
            ulonglong2 v = *reinterpret_cast<const ulonglong2*>(s_x + (J0 + rr) * STRIDE + 4 * mm);
            if (rr < 9)            { fma2(acc[rr], v.x, w0.x);     fma2(acc[rr], v.y, w0.y); }
            if (rr >= 1 && rr <= 9){ fma2(acc[rr - 1], v.x, w1.x); fma2(acc[rr - 1], v.y, w1.y); }
            if (rr >= 2)           { fma2(acc[rr - 2], v.x, w2.x); fma2(acc[rr - 2], v.y, w2.y); }
        }
    }
#pragma unroll
    for (int j = 0; j < 9; j++)
        h1T[(J0 + j) * 32] = fmaxf(hsum2(acc[j]) + bv, 0.f);
}

// ---------------------------------------------------------------------------
// conv2 half-pass over channel QUADS: 8 outputs j = J0..J0+7, returns partial
// relu-sum for pooling.
// ---------------------------------------------------------------------------
template <int J0>
DEVINL float conv2Q_half(const float* __restrict__ h1T, const float* __restrict__ s_w,
                         float bv) {
    ull acc[8];
#pragma unroll
    for (int j = 0; j < 8; j++) acc[j] = 0ull;
#pragma unroll 2
    for (int mm = 0; mm < 8; mm++) {
        ulonglong2 w0 = *reinterpret_cast<const ulonglong2*>(s_w + (3 * mm + 0) * 128);
        ulonglong2 w1 = *reinterpret_cast<const ulonglong2*>(s_w + (3 * mm + 1) * 128);
        ulonglong2 w2 = *reinterpret_cast<const ulonglong2*>(s_w + (3 * mm + 2) * 128);
#pragma unroll
        for (int rr = 0; rr < 10; rr++) {
            ulonglong2 v = *reinterpret_cast<const ulonglong2*>(h1T + (J0 + rr) * 32 + 4 * mm);
            if (rr < 8)            { fma2(acc[rr], v.x, w0.x);     fma2(acc[rr], v.y, w0.y); }
            if (rr >= 1 && rr <= 8){ fma2(acc[rr - 1], v.x, w1.x); fma2(acc[rr - 1], v.y, w1.y); }
            if (rr >= 2)           { fma2(acc[rr - 2], v.x, w2.x); fma2(acc[rr - 2], v.y, w2.y); }
        }
    }
    float s = 0.f;
#pragma unroll
    for (int j = 0; j < 8; j++)
        s += fmaxf(hsum2(acc[j]) + bv, 0.f);
    return s;
}

// ---------------------------------------------------------------------------
// Encoder kernel: warp = one window; 3 blocks/SM target.
// ---------------------------------------------------------------------------
__global__ void __launch_bounds__(256, 3) enc_kernel(
    const float* __restrict__ pressure, const float* __restrict__ torque,
    const float* __restrict__ frag,
    const float* __restrict__ pw1, const float* __restrict__ pb1,
    const float* __restrict__ pw2, const float* __restrict__ pb2,
    const float* __restrict__ tw1, const float* __restrict__ tb1,
    const float* __restrict__ tw2, const float* __restrict__ tb2,
    const float* __restrict__ fw, const float* __restrict__ fb,
    const float* __restrict__ prw, const float* __restrict__ prb,
    const float* __restrict__ Wih, const float* __restrict__ bih,
    const float* __restrict__ bhh) {
    extern __shared__ float sm[];
    const int tid = threadIdx.x;
    const int lane = tid & 31;
    const int warp = tid >> 5;

    // ---- stage weights ----
    for (int t = tid; t < 32 * 3 * 3; t += 256) {         // conv1p pairs
        int o = t / 9, rem = t % 9, m = rem / 3, k = rem % 3;
        int di = OFF_W1P + (3 * m + k) * 64 + 2 * o;
        sm[di]     = pw1[(o * NP + 2 * m) * 3 + k];
        sm[di + 1] = pw1[(o * NP + 2 * m + 1) * 3 + k];
    }
    for (int t = tid; t < 32 * 3 * 3; t += 256) {         // conv1t quads
        int o = t / 9, rem = t % 9, mm = rem / 3, k = rem % 3;
        int di = OFF_W1T + (3 * mm + k) * 128 + 4 * o;
#pragma unroll
        for (int q = 0; q < 4; q++)
            sm[di + q] = tw1[(o * NT + 4 * mm + q) * 3 + k];
    }
    for (int t = tid; t < 32 * 8 * 3; t += 256) {         // conv2 quads
        int o = t / 24, rem = t % 24, mm = rem / 3, k = rem % 3;
        int di = (3 * mm + k) * 128 + 4 * o;
#pragma unroll
        for (int q = 0; q < 4; q++) {
            int si = (o * CC + 4 * mm + q) * 3 + k;
            sm[OFF_W2P + di + q] = pw2[si];
            sm[OFF_W2T + di + q] = tw2[si];
        }
    }
    if (tid < 32) {
        sm[OFF_B1P + tid] = pb1[tid]; sm[OFF_B1T + tid] = tb1[tid];
        sm[OFF_B2P + tid] = pb2[tid]; sm[OFF_B2T + tid] = tb2[tid];
    }
    sm[OFF_BIAS + tid] = bih[tid] + bhh[tid];
    __syncthreads();

    const int wi = blockIdx.x * 8 + warp;
    const int b = wi >> 8;

    float* sxp = sm + OFF_XP + warp * 128;
    float* sxt = sm + OFF_XT + warp * 256;
    float* sh1 = sm + OFF_H1 + warp * 576;
    float* sft = sm + OFF_CAT + warp * 80;
    float* spj = sm + OFF_PRJ + warp * 64;

    // ---- load window inputs (raw [pos][ch] layout kept) ----
    {
        const float4* gp4 = reinterpret_cast<const float4*>(pressure + wi * 120);
        if (lane < 30) reinterpret_cast<float4*>(sxp)[lane] = gp4[lane];
        const float4* gt4 = reinterpret_cast<const float4*>(torque + wi * 240);
        reinterpret_cast<float4*>(sxt)[lane] = gt4[lane];
        if (lane < 28) reinterpret_cast<float4*>(sxt)[lane + 32] = gt4[lane + 32];
    }
    __syncwarp();

    // ---- pressure: conv1 -> h1T -> conv2 -> pooled ----
    conv1P_half<3, NP, 0>(sxp, sm + OFF_W1P + 2 * lane, sm[OFF_B1P + lane], sh1 + lane);
    conv1P_half<3, NP, 9>(sxp, sm + OFF_W1P + 2 * lane, sm[OFF_B1P + lane], sh1 + lane);
    __syncwarp();
    float poolp = conv2Q_half<0>(sh1, sm + OFF_W2P + 4 * lane, sm[OFF_B2P + lane]);
    poolp      += conv2Q_half<8>(sh1, sm + OFF_W2P + 4 * lane, sm[OFF_B2P + lane]);
    __syncwarp();

    // ---- torque: conv1 -> h1T -> conv2 -> pooled ----
    conv1Q_half<3, NT, 0>(sxt, sm + OFF_W1T + 4 * lane, sm[OFF_B1T + lane], sh1 + lane);
    conv1Q_half<3, NT, 9>(sxt, sm + OFF_W1T + 4 * lane, sm[OFF_B1T + lane], sh1 + lane);
    __syncwarp();
    float poolt = conv2Q_half<0>(sh1, sm + OFF_W2T + 4 * lane, sm[OFF_B2T + lane]);
    poolt      += conv2Q_half<8>(sh1, sm + OFF_W2T + 4 * lane, sm[OFF_B2T + lane]);

    sft[lane] = poolp * (1.f / 16.f);
    sft[32 + lane] = poolt * (1.f / 16.f);
    if (lane < FD) sft[64 + lane] = fmaxf(fmaf(frag[b], fw[lane], fb[lane]), 0.f);
    __syncwarp();

    // ---- projection: 2 outputs per lane, packed dot-72 ----
    {
        ull a0 = 0ull, a1 = 0ull, b0 = 0ull, b1 = 0ull;
        const ull* w0 = reinterpret_cast<const ull*>(prw + lane * 72);
        const ull* w1 = reinterpret_cast<const ull*>(prw + (lane + 32) * 72);
        const ull* cv = reinterpret_cast<const ull*>(sft);
#pragma unroll
        for (int q = 0; q < 36; q += 2) {
            ull x0 = cv[q], x1 = cv[q + 1];
            fma2(a0, w0[q], x0); fma2(b0, w0[q + 1], x1);
            fma2(a1, w1[q], x0); fma2(b1, w1[q + 1], x1);
        }
        add2(a0, a0, b0);
        add2(a1, a1, b1);
        spj[lane]      = fmaxf(hsum2(a0) + prb[lane], 0.f);
        spj[lane + 32] = fmaxf(hsum2(a1) + prb[lane + 32], 0.f);
    }
    __syncthreads();

    // ---- xg: gate tid for all 8 windows; Wih row cached per k-half ----
    {
        ull part[8];
        const int wbase = blockIdx.x * 8;
        const float bias = sm[OFF_BIAS + tid];
#pragma unroll
        for (int half = 0; half < 2; half++) {
            ull wv[16];
            const ulonglong2* wr =
                reinterpret_cast<const ulonglong2*>(Wih + tid * PROJ + half * 32);
#pragma unroll
            for (int q = 0; q < 8; q++) {
                ulonglong2 v = wr[q];
                wv[2 * q] = v.x; wv[2 * q + 1] = v.y;
            }
#pragma unroll
            for (int win = 0; win < 8; win++) {
                const ulonglong2* fr =
                    reinterpret_cast<const ulonglong2*>(sm + OFF_PRJ + win * 64 + half * 32);
                ull a0 = 0ull, a1 = 0ull, a2 = 0ull, a3 = 0ull;
#pragma unroll
                for (int q = 0; q < 8; q++) {
                    ulonglong2 fv = fr[q];
                    if ((q & 1) == 0) { fma2(a0, wv[2 * q], fv.x); fma2(a1, wv[2 * q + 1], fv.y); }
                    else              { fma2(a2, wv[2 * q], fv.x); fma2(a3, wv[2 * q + 1], fv.y); }
                }
                add2(a0, a0, a2);
                add2(a1, a1, a3);
                add2(a0, a0, a1);
                if (half == 0) {
                    ull binit = pack2(bias, 0.f);
                    add2(part[win], a0, binit);
                } else {
                    add2(part[win], part[win], a0);
                    g_xg[(wbase + win) * NG + tid] = hsum2(part[win]);
                }
            }
        }
    }
}

// ---------------------------------------------------------------------------
// LSTM kernel: one block per batch row, 256 threads = one gate each.
// Activation pre-barrier; smem gact exchange; 8-way split accumulators.
// ---------------------------------------------------------------------------
__global__ void __launch_bounds__(256) lstm_kernel(
    const float* __restrict__ Whh, float* __restrict__ out) {
    __shared__ __align__(16) float s_h[PROJ];
    __shared__ float s_gact[NG];

    const int tid = threadIdx.x;
    const int b = blockIdx.x;
    const int cls = tid >> 6;  // 0:i 1:f 2:g 3:o

    ull wreg[PROJ / 2];
    {
        const ulonglong2* w2 = reinterpret_cast<const ulonglong2*>(Whh + tid * PROJ);
#pragma unroll
        for (int q = 0; q < PROJ / 4; q++) {
            ulonglong2 v = w2[q];
            wreg[2 * q] = v.x;
            wreg[2 * q + 1] = v.y;
        }
    }

    if (tid < PROJ) s_h[tid] = 0.f;
    float c = 0.f;

    const float* xg = g_xg + b * T * NG;
    float* hs = g_hs + b * T * PROJ;
    float xnext = xg[tid];
    __syncthreads();

    for (int t = 0; t < T; t++) {
        float xcur = xnext;
        int tn = (t + 1 < T) ? (t + 1) : (T - 1);
        xnext = xg[tn * NG + tid];

        // 8 accumulator chains (depth 4), then 3-level reduction
        ull a[8];
        a[0] = pack2(xcur, 0.f);
#pragma unroll
        for (int i = 1; i < 8; i++) a[i] = 0ull;
        const ulonglong2* h2 = reinterpret_cast<const ulonglong2*>(s_h);
#pragma unroll
        for (int q = 0; q < 16; q++) {
            ulonglong2 hv = h2[q];
            fma2(a[(2 * q) & 7], wreg[2 * q], hv.x);
            fma2(a[(2 * q + 1) & 7], wreg[2 * q + 1], hv.y);
        }
        add2(a[0], a[0], a[4]);
        add2(a[1], a[1], a[5]);
        add2(a[2], a[2], a[6]);
        add2(a[3], a[3], a[7]);
        add2(a[0], a[0], a[2]);
        add2(a[1], a[1], a[3]);
        add2(a[0], a[0], a[1]);
        float g = hsum2(a[0]);
        s_gact[tid] = (cls == 2) ? tanh_(g) : sigm(g);
        __syncthreads();

        if (tid < PROJ) {
            float ai = s_gact[tid];
            float af = s_gact[PROJ + tid];
            float ag = s_gact[2 * PROJ + tid];
            float ao = s_gact[3 * PROJ + tid];
            c = fmaf(af, c, ai * ag);
            float h = ao * tanh_(c);
            s_h[tid] = h;
            hs[t * PROJ + tid] = h;
        }
        __syncthreads();
    }

    if (tid < PROJ) {
        out[B * T * 4 + b * PROJ + tid] = s_h[tid];             // hT
        out[B * T * 4 + B * PROJ + b * PROJ + tid] = c;         // cT
    }
}

// ---------------------------------------------------------------------------
// Head kernel: out[wi, m] = sigmoid(h[wi] . hw[m] + hb[m]), fully parallel.
// ---------------------------------------------------------------------------
__global__ void __launch_bounds__(256) head_kernel(
    const float* __restrict__ hw, const float* __restrict__ hb,
    float* __restrict__ out) {
    __shared__ __align__(16) float s_hw[4 * PROJ];
    __shared__ float s_hb[4];
    const int tid = threadIdx.x;
    s_hw[tid] = hw[tid];
    if (tid < 4) s_hb[tid] = hb[tid];
    __syncthreads();

    const int gid = blockIdx.x * 256 + tid;
    const int wi = gid >> 2, m = gid & 3;
    const float4* hr = reinterpret_cast<const float4*>(g_hs + wi * PROJ);
    const float4* wr = reinterpret_cast<const float4*>(s_hw) + m * 16;
    float a0 = s_hb[m], a1 = 0.f;
#pragma unroll
    for (int q = 0; q < 16; q += 2) {
        float4 h0 = hr[q], w0 = wr[q];
        float4 h1 = hr[q + 1], w1 = wr[q + 1];
        a0 = fmaf(h0.x, w0.x, a0); a0 = fmaf(h0.y, w0.y, a0);
        a0 = fmaf(h0.z, w0.z, a0); a0 = fmaf(h0.w, w0.w, a0);
        a1 = fmaf(h1.x, w1.x, a1); a1 = fmaf(h1.y, w1.y, a1);
        a1 = fmaf(h1.z, w1.z, a1); a1 = fmaf(h1.w, w1.w, a1);
    }
    out[gid] = sigm(a0 + a1);
}

// ---------------------------------------------------------------------------
extern "C" void kernel_launch(void* const* d_in, const int* in_sizes, int n_in,
                              void* d_out, int out_size) {
    const float* pressure = (const float*)d_in[0];
    const float* torque   = (const float*)d_in[1];
    const float* frag     = (const float*)d_in[2];
    const float* pw1 = (const float*)d_in[3];
    const float* pb1 = (const float*)d_in[4];
    const float* pw2 = (const float*)d_in[5];
    const float* pb2 = (const float*)d_in[6];
    const float* tw1 = (const float*)d_in[7];
    const float* tb1 = (const float*)d_in[8];
    const float* tw2 = (const float*)d_in[9];
    const float* tb2 = (const float*)d_in[10];
    const float* fw  = (const float*)d_in[11];
    const float* fb  = (const float*)d_in[12];
    const float* prw = (const float*)d_in[13];
    const float* prb = (const float*)d_in[14];
    const float* Wih = (const float*)d_in[15];
    const float* Whh = (const float*)d_in[16];
    const float* bih = (const float*)d_in[17];
    const float* bhh = (const float*)d_in[18];
    const float* hw  = (const float*)d_in[19];
    const float* hb  = (const float*)d_in[20];

    static bool attr_set = false;
    if (!attr_set) {
        cudaFuncSetAttribute(enc_kernel, cudaFuncAttributeMaxDynamicSharedMemorySize,
                             SMEM_BYTES);
        attr_set = true;
    }

    enc_kernel<<<NWIN / 8, 256, SMEM_BYTES>>>(pressure, torque, frag,
                                              pw1, pb1, pw2, pb2, tw1, tb1, tw2, tb2,
                                              fw, fb, prw, prb, Wih, bih, bhh);
    lstm_kernel<<<B, 256>>>(Whh, (float*)d_out);
    head_kernel<<<(B * T * 4) / 256, 256>>>(hw, hb, (float*)d_out);
}

// round 8
// speedup vs baseline: 1.0297x; 1.0297x over previous
#include <cuda_runtime.h>

#define DEVINL __device__ __forceinline__
typedef unsigned long long ull;

constexpr int B = 64, T = 256, W = 20, NP = 6, NT = 12, CC = 32, FD = 8, PROJ = 64;
constexpr int NG = 4 * PROJ;            // 256 gates
constexpr int NWIN = B * T;             // 16384

// scratch
__device__ float g_xg[NWIN * NG];       // 16 MB: xg = feat @ Wih^T + (bih+bhh)
__device__ float g_hs[NWIN * PROJ];     // 4 MB: per-step hidden states

DEVINL void fma2(ull& d, ull a, ull b) {
    asm("fma.rn.f32x2 %0, %1, %2, %0;" : "+l"(d) : "l"(a), "l"(b));
}
DEVINL void add2(ull& d, ull a, ull b) {
    asm("add.rn.f32x2 %0, %1, %2;" : "=l"(d) : "l"(a), "l"(b));
}
DEVINL float hsum2(ull a) {
    float lo, hi;
    asm("mov.b64 {%0,%1}, %2;" : "=f"(lo), "=f"(hi) : "l"(a));
    return lo + hi;
}
DEVINL ull pack2(float lo, float hi) {
    ull r;
    asm("mov.b64 %0, {%1,%2};" : "=l"(r) : "f"(lo), "f"(hi));
    return r;
}

DEVINL float sigm(float x) { return __fdividef(1.f, 1.f + __expf(-x)); }
DEVINL float tanh_(float x) { return __fdividef(2.f, 1.f + __expf(-2.f * x)) - 1.f; }

// ---------------------------------------------------------------------------
// smem layout (floats) — dynamic shared
//   conv1p weights: channel-PAIRS  [(3m+k)*64 + 2o]
//   conv1t / conv2 weights: channel-QUADS [(3mm+k)*128 + 4o]
// ---------------------------------------------------------------------------
constexpr int OFF_W1P  = 0;                       // 576
constexpr int OFF_W1T  = OFF_W1P + 576;           // 1152
constexpr int OFF_W2P  = OFF_W1T + 1152;          // 3072
constexpr int OFF_W2T  = OFF_W2P + 3072;          // 3072
constexpr int OFF_B1P  = OFF_W2T + 3072;          // 32
constexpr int OFF_B1T  = OFF_B1P + 32;            // 32
constexpr int OFF_B2P  = OFF_B1T + 32;            // 32
constexpr int OFF_B2T  = OFF_B2P + 32;            // 32
constexpr int OFF_BIAS = OFF_B2T + 32;            // 256
constexpr int OFF_XP   = OFF_BIAS + 256;          // 8 * 128
constexpr int OFF_XT   = OFF_XP + 8 * 128;        // 8 * 256
constexpr int OFF_H1   = OFF_XT + 8 * 256;        // 8 * 576
constexpr int OFF_CAT  = OFF_H1 + 8 * 576;        // 8 * 80
constexpr int OFF_PRJ  = OFF_CAT + 8 * 80;        // 8 * 64
constexpr int SMEM_FLOATS = OFF_PRJ + 8 * 64;
constexpr int SMEM_BYTES = SMEM_FLOATS * 4;

// ---------------------------------------------------------------------------
// conv1 over channel PAIRS (pressure, stride 6). Full 18-output pass.
// ---------------------------------------------------------------------------
template <int NPAIR, int STRIDE>
DEVINL void conv1P(const float* __restrict__ s_x, const float* __restrict__ s_w,
                   float bv, float* __restrict__ h1T) {
    ull acc[18];
#pragma unroll
    for (int j = 0; j < 18; j++) acc[j] = 0ull;
#pragma unroll
    for (int m = 0; m < NPAIR; m++) {
        ull w0 = *reinterpret_cast<const ull*>(s_w + (3 * m + 0) * 64);
        ull w1 = *reinterpret_cast<const ull*>(s_w + (3 * m + 1) * 64);
        ull w2 = *reinterpret_cast<const ull*>(s_w + (3 * m + 2) * 64);
#pragma unroll
        for (int j = 0; j < 20; j++) {
            ull v = *reinterpret_cast<const ull*>(s_x + j * STRIDE + 2 * m);
            if (j < 18) fma2(acc[j], v, w0);
            if (j >= 1 && j <= 18) fma2(acc[j - 1], v, w1);
            if (j >= 2) fma2(acc[j - 2], v, w2);
        }
    }
#pragma unroll
    for (int j = 0; j < 18; j++)
        h1T[j * 32] = fmaxf(hsum2(acc[j]) + bv, 0.f);
}

// ---------------------------------------------------------------------------
// conv1 over channel QUADS (torque, stride 12). Full 18-output pass.
// ---------------------------------------------------------------------------
template <int NQUAD, int STRIDE>
DEVINL void conv1Q(const float* __restrict__ s_x, const float* __restrict__ s_w,
                   float bv, float* __restrict__ h1T) {
    ull acc[18];
#pragma unroll
    for (int j = 0; j < 18; j++) acc[j] = 0ull;
#pragma unroll
    for (int mm = 0; mm < NQUAD; mm++) {
        ulonglong2 w0 = *reinterpret_cast<const ulonglong2*>(s_w + (3 * mm + 0) * 128);
        ulonglong2 w1 = *reinterpret_cast<const ulonglong2*>(s_w + (3 * mm + 1) * 128);
        ulonglong2 w2 = *reinterpret_cast<const ulonglong2*>(s_w + (3 * mm + 2) * 128);
#pragma unroll
        for (int j = 0; j < 20; j++) {
            ulonglong2 v = *reinterpret_cast<const ulonglong2*>(s_x + j * STRIDE + 4 * mm);
            if (j < 18)            { fma2(acc[j], v.x, w0.x);     fma2(acc[j], v.y, w0.y); }
            if (j >= 1 && j <= 18) { fma2(acc[j - 1], v.x, w1.x); fma2(acc[j - 1], v.y, w1.y); }
            if (j >= 2)            { fma2(acc[j - 2], v.x, w2.x); fma2(acc[j - 2], v.y, w2.y); }
        }
    }
#pragma unroll
    for (int j = 0; j < 18; j++)
        h1T[j * 32] = fmaxf(hsum2(acc[j]) + bv, 0.f);
}

// ---------------------------------------------------------------------------
// conv2 over channel QUADS + relu + mean pool. Full 16-output pass.
// ---------------------------------------------------------------------------
DEVINL float conv2Q(const float* __restrict__ h1T, const float* __restrict__ s_w,
                    float bv) {
    ull acc[16];
#pragma unroll
    for (int j = 0; j < 16; j++) acc[j] = 0ull;
#pragma unroll 2
    for (int mm = 0; mm < 8; mm++) {
        ulonglong2 w0 = *reinterpret_cast<const ulonglong2*>(s_w + (3 * mm + 0) * 128);
        ulonglong2 w1 = *reinterpret_cast<const ulonglong2*>(s_w + (3 * mm + 1) * 128);
        ulonglong2 w2 = *reinterpret_cast<const ulonglong2*>(s_w + (3 * mm + 2) * 128);
#pragma unroll
        for (int j = 0; j < 18; j++) {
            ulonglong2 v = *reinterpret_cast<const ulonglong2*>(h1T + j * 32 + 4 * mm);
            if (j < 16)            { fma2(acc[j], v.x, w0.x);     fma2(acc[j], v.y, w0.y); }
            if (j >= 1 && j <= 16) { fma2(acc[j - 1], v.x, w1.x); fma2(acc[j - 1], v.y, w1.y); }
            if (j >= 2)            { fma2(acc[j - 2], v.x, w2.x); fma2(acc[j - 2], v.y, w2.y); }
        }
    }
    float s = 0.f;
#pragma unroll
    for (int j = 0; j < 16; j++)
        s += fmaxf(hsum2(acc[j]) + bv, 0.f);
    return s * (1.f / 16.f);
}

// ---------------------------------------------------------------------------
// Encoder kernel: warp = one window; 3 blocks/SM, r6 instruction counts.
// ---------------------------------------------------------------------------
__global__ void __launch_bounds__(256, 3) enc_kernel(
    const float* __restrict__ pressure, const float* __restrict__ torque,
    const float* __restrict__ frag,
    const float* __restrict__ pw1, const float* __restrict__ pb1,
    const float* __restrict__ pw2, const float* __restrict__ pb2,
    const float* __restrict__ tw1, const float* __restrict__ tb1,
    const float* __restrict__ tw2, const float* __restrict__ tb2,
    const float* __restrict__ fw, const float* __restrict__ fb,
    const float* __restrict__ prw, const float* __restrict__ prb,
    const float* __restrict__ Wih, const float* __restrict__ bih,
    const float* __restrict__ bhh) {
    extern __shared__ float sm[];
    const int tid = threadIdx.x;
    const int lane = tid & 31;
    const int warp = tid >> 5;

    // ---- stage weights ----
    for (int t = tid; t < 32 * 3 * 3; t += 256) {         // conv1p pairs
        int o = t / 9, rem = t % 9, m = rem / 3, k = rem % 3;
        int di = OFF_W1P + (3 * m + k) * 64 + 2 * o;
        sm[di]     = pw1[(o * NP + 2 * m) * 3 + k];
        sm[di + 1] = pw1[(o * NP + 2 * m + 1) * 3 + k];
    }
    for (int t = tid; t < 32 * 3 * 3; t += 256) {         // conv1t quads
        int o = t / 9, rem = t % 9, mm = rem / 3, k = rem % 3;
        int di = OFF_W1T + (3 * mm + k) * 128 + 4 * o;
#pragma unroll
        for (int q = 0; q < 4; q++)
            sm[di + q] = tw1[(o * NT + 4 * mm + q) * 3 + k];
    }
    for (int t = tid; t < 32 * 8 * 3; t += 256) {         // conv2 quads
        int o = t / 24, rem = t % 24, mm = rem / 3, k = rem % 3;
        int di = (3 * mm + k) * 128 + 4 * o;
#pragma unroll
        for (int q = 0; q < 4; q++) {
            int si = (o * CC + 4 * mm + q) * 3 + k;
            sm[OFF_W2P + di + q] = pw2[si];
            sm[OFF_W2T + di + q] = tw2[si];
        }
    }
    if (tid < 32) {
        sm[OFF_B1P + tid] = pb1[tid]; sm[OFF_B1T + tid] = tb1[tid];
        sm[OFF_B2P + tid] = pb2[tid]; sm[OFF_B2T + tid] = tb2[tid];
    }
    sm[OFF_BIAS + tid] = bih[tid] + bhh[tid];
    __syncthreads();

    const int wi = blockIdx.x * 8 + warp;
    const int b = wi >> 8;

    float* sxp = sm + OFF_XP + warp * 128;
    float* sxt = sm + OFF_XT + warp * 256;
    float* sh1 = sm + OFF_H1 + warp * 576;
    float* sft = sm + OFF_CAT + warp * 80;
    float* spj = sm + OFF_PRJ + warp * 64;

    // ---- load window inputs (raw [pos][ch] layout kept) ----
    {
        const float4* gp4 = reinterpret_cast<const float4*>(pressure + wi * 120);
        if (lane < 30) reinterpret_cast<float4*>(sxp)[lane] = gp4[lane];
        const float4* gt4 = reinterpret_cast<const float4*>(torque + wi * 240);
        reinterpret_cast<float4*>(sxt)[lane] = gt4[lane];
        if (lane < 28) reinterpret_cast<float4*>(sxt)[lane + 32] = gt4[lane + 32];
    }
    __syncwarp();

    // ---- pressure: conv1 -> h1T -> conv2 -> pooled ----
    conv1P<3, NP>(sxp, sm + OFF_W1P + 2 * lane, sm[OFF_B1P + lane], sh1 + lane);
    __syncwarp();
    float poolp = conv2Q(sh1, sm + OFF_W2P + 4 * lane, sm[OFF_B2P + lane]);
    __syncwarp();

    // ---- torque: conv1 -> h1T -> conv2 -> pooled ----
    conv1Q<3, NT>(sxt, sm + OFF_W1T + 4 * lane, sm[OFF_B1T + lane], sh1 + lane);
    __syncwarp();
    float poolt = conv2Q(sh1, sm + OFF_W2T + 4 * lane, sm[OFF_B2T + lane]);

    sft[lane] = poolp;
    sft[32 + lane] = poolt;
    if (lane < FD) sft[64 + lane] = fmaxf(fmaf(frag[b], fw[lane], fb[lane]), 0.f);
    __syncwarp();

    // ---- projection: 2 outputs per lane, packed dot-72 ----
    {
        ull a0 = 0ull, a1 = 0ull, b0 = 0ull, b1 = 0ull;
        const ull* w0 = reinterpret_cast<const ull*>(prw + lane * 72);
        const ull* w1 = reinterpret_cast<const ull*>(prw + (lane + 32) * 72);
        const ull* cv = reinterpret_cast<const ull*>(sft);
#pragma unroll
        for (int q = 0; q < 36; q += 2) {
            ull x0 = cv[q], x1 = cv[q + 1];
            fma2(a0, w0[q], x0); fma2(b0, w0[q + 1], x1);
            fma2(a1, w1[q], x0); fma2(b1, w1[q + 1], x1);
        }
        add2(a0, a0, b0);
        add2(a1, a1, b1);
        spj[lane]      = fmaxf(hsum2(a0) + prb[lane], 0.f);
        spj[lane + 32] = fmaxf(hsum2(a1) + prb[lane + 32], 0.f);
    }
    __syncthreads();

    // ---- xg: gate tid for all 8 windows; Wih cached per k-half (reg diet) ----
    {
        ull part[8];
        const int wbase = blockIdx.x * 8;
        const float bias = sm[OFF_BIAS + tid];
#pragma unroll
        for (int half = 0; half < 2; half++) {
            ull wv[16];
            const ulonglong2* wr =
                reinterpret_cast<const ulonglong2*>(Wih + tid * PROJ + half * 32);
#pragma unroll
            for (int q = 0; q < 8; q++) {
                ulonglong2 v = wr[q];
                wv[2 * q] = v.x; wv[2 * q + 1] = v.y;
            }
#pragma unroll
            for (int win = 0; win < 8; win++) {
                const ulonglong2* fr =
                    reinterpret_cast<const ulonglong2*>(sm + OFF_PRJ + win * 64 + half * 32);
                ull a0 = 0ull, a1 = 0ull, a2 = 0ull, a3 = 0ull;
#pragma unroll
                for (int q = 0; q < 8; q++) {
                    ulonglong2 fv = fr[q];
                    if ((q & 1) == 0) { fma2(a0, wv[2 * q], fv.x); fma2(a1, wv[2 * q + 1], fv.y); }
                    else              { fma2(a2, wv[2 * q], fv.x); fma2(a3, wv[2 * q + 1], fv.y); }
                }
                add2(a0, a0, a2);
                add2(a1, a1, a3);
                add2(a0, a0, a1);
                if (half == 0) {
                    ull binit = pack2(bias, 0.f);
                    add2(part[win], a0, binit);
                } else {
                    add2(part[win], part[win], a0);
                    g_xg[(wbase + win) * NG + tid] = hsum2(part[win]);
                }
            }
        }
    }
}

// ---------------------------------------------------------------------------
// LSTM kernel: one block per batch row, 256 threads = one gate each.
// Activation pre-barrier; smem gact exchange; 8-way split accumulators.
// ---------------------------------------------------------------------------
__global__ void __launch_bounds__(256) lstm_kernel(
    const float* __restrict__ Whh, float* __restrict__ out) {
    __shared__ __align__(16) float s_h[PROJ];
    __shared__ float s_gact[NG];

    const int tid = threadIdx.x;
    const int b = blockIdx.x;
    const int cls = tid >> 6;  // 0:i 1:f 2:g 3:o

    ull wreg[PROJ / 2];
    {
        const ulonglong2* w2 = reinterpret_cast<const ulonglong2*>(Whh + tid * PROJ);
#pragma unroll
        for (int q = 0; q < PROJ / 4; q++) {
            ulonglong2 v = w2[q];
            wreg[2 * q] = v.x;
            wreg[2 * q + 1] = v.y;
        }
    }

    if (tid < PROJ) s_h[tid] = 0.f;
    float c = 0.f;

    const float* xg = g_xg + b * T * NG;
    float* hs = g_hs + b * T * PROJ;
    float xnext = xg[tid];
    __syncthreads();

    for (int t = 0; t < T; t++) {
        float xcur = xnext;
        int tn = (t + 1 < T) ? (t + 1) : (T - 1);
        xnext = xg[tn * NG + tid];

        // 8 accumulator chains (depth 4), then 3-level reduction
        ull a[8];
        a[0] = pack2(xcur, 0.f);
#pragma unroll
        for (int i = 1; i < 8; i++) a[i] = 0ull;
        const ulonglong2* h2 = reinterpret_cast<const ulonglong2*>(s_h);
#pragma unroll
        for (int q = 0; q < 16; q++) {
            ulonglong2 hv = h2[q];
            fma2(a[(2 * q) & 7], wreg[2 * q], hv.x);
            fma2(a[(2 * q + 1) & 7], wreg[2 * q + 1], hv.y);
        }
        add2(a[0], a[0], a[4]);
        add2(a[1], a[1], a[5]);
        add2(a[2], a[2], a[6]);
        add2(a[3], a[3], a[7]);
        add2(a[0], a[0], a[2]);
        add2(a[1], a[1], a[3]);
        add2(a[0], a[0], a[1]);
        float g = hsum2(a[0]);
        s_gact[tid] = (cls == 2) ? tanh_(g) : sigm(g);
        __syncthreads();

        if (tid < PROJ) {
            float ai = s_gact[tid];
            float af = s_gact[PROJ + tid];
            float ag = s_gact[2 * PROJ + tid];
            float ao = s_gact[3 * PROJ + tid];
            c = fmaf(af, c, ai * ag);
            float h = ao * tanh_(c);
            s_h[tid] = h;
            hs[t * PROJ + tid] = h;
        }
        __syncthreads();
    }

    if (tid < PROJ) {
        out[B * T * 4 + b * PROJ + tid] = s_h[tid];             // hT
        out[B * T * 4 + B * PROJ + b * PROJ + tid] = c;         // cT
    }
}

// ---------------------------------------------------------------------------
// Head kernel: out[wi, m] = sigmoid(h[wi] . hw[m] + hb[m]), fully parallel.
// ---------------------------------------------------------------------------
__global__ void __launch_bounds__(256) head_kernel(
    const float* __restrict__ hw, const float* __restrict__ hb,
    float* __restrict__ out) {
    __shared__ __align__(16) float s_hw[4 * PROJ];
    __shared__ float s_hb[4];
    const int tid = threadIdx.x;
    s_hw[tid] = hw[tid];
    if (tid < 4) s_hb[tid] = hb[tid];
    __syncthreads();

    const int gid = blockIdx.x * 256 + tid;
    const int wi = gid >> 2, m = gid & 3;
    const float4* hr = reinterpret_cast<const float4*>(g_hs + wi * PROJ);
    const float4* wr = reinterpret_cast<const float4*>(s_hw) + m * 16;
    float a0 = s_hb[m], a1 = 0.f;
#pragma unroll
    for (int q = 0; q < 16; q += 2) {
        float4 h0 = hr[q], w0 = wr[q];
        float4 h1 = hr[q + 1], w1 = wr[q + 1];
        a0 = fmaf(h0.x, w0.x, a0); a0 = fmaf(h0.y, w0.y, a0);
        a0 = fmaf(h0.z, w0.z, a0); a0 = fmaf(h0.w, w0.w, a0);
        a1 = fmaf(h1.x, w1.x, a1); a1 = fmaf(h1.y, w1.y, a1);
        a1 = fmaf(h1.z, w1.z, a1); a1 = fmaf(h1.w, w1.w, a1);
    }
    out[gid] = sigm(a0 + a1);
}

// ---------------------------------------------------------------------------
extern "C" void kernel_launch(void* const* d_in, const int* in_sizes, int n_in,
                              void* d_out, int out_size) {
    const float* pressure = (const float*)d_in[0];
    const float* torque   = (const float*)d_in[1];
    const float* frag     = (const float*)d_in[2];
    const float* pw1 = (const float*)d_in[3];
    const float* pb1 = (const float*)d_in[4];
    const float* pw2 = (const float*)d_in[5];
    const float* pb2 = (const float*)d_in[6];
    const float* tw1 = (const float*)d_in[7];
    const float* tb1 = (const float*)d_in[8];
    const float* tw2 = (const float*)d_in[9];
    const float* tb2 = (const float*)d_in[10];
    const float* fw  = (const float*)d_in[11];
    const float* fb  = (const float*)d_in[12];
    const float* prw = (const float*)d_in[13];
    const float* prb = (const float*)d_in[14];
    const float* Wih = (const float*)d_in[15];
    const float* Whh = (const float*)d_in[16];
    const float* bih = (const float*)d_in[17];
    const float* bhh = (const float*)d_in[18];
    const float* hw  = (const float*)d_in[19];
    const float* hb  = (const float*)d_in[20];

    static bool attr_set = false;
    if (!attr_set) {
        cudaFuncSetAttribute(enc_kernel, cudaFuncAttributeMaxDynamicSharedMemorySize,
                             SMEM_BYTES);
        attr_set = true;
    }

    enc_kernel<<<NWIN / 8, 256, SMEM_BYTES>>>(pressure, torque, frag,
                                              pw1, pb1, pw2, pb2, tw1, tb1, tw2, tb2,
                                              fw, fb, prw, prb, Wih, bih, bhh);
    lstm_kernel<<<B, 256>>>(Whh, (float*)d_out);
    head_kernel<<<(B * T * 4) / 256, 256>>>(hw, hb, (float*)d_out);
}

// round 9
// speedup vs baseline: 1.1245x; 1.0921x over previous
#include <cuda_runtime.h>

#define DEVINL __device__ __forceinline__
typedef unsigned long long ull;

constexpr int B = 64, T = 256, W = 20, NP = 6, NT = 12, CC = 32, FD = 8, PROJ = 64;
constexpr int NG = 4 * PROJ;            // 256 gates
constexpr int NWIN = B * T;             // 16384
constexpr int WPB = 16;                 // windows per block (2 per warp)

// scratch
__device__ float g_xg[NWIN * NG];       // 16 MB: xg = feat @ Wih^T + (bih+bhh)
__device__ float g_hs[NWIN * PROJ];     // 4 MB: per-step hidden states

DEVINL void fma2(ull& d, ull a, ull b) {
    asm("fma.rn.f32x2 %0, %1, %2, %0;" : "+l"(d) : "l"(a), "l"(b));
}
DEVINL void add2(ull& d, ull a, ull b) {
    asm("add.rn.f32x2 %0, %1, %2;" : "=l"(d) : "l"(a), "l"(b));
}
DEVINL float hsum2(ull a) {
    float lo, hi;
    asm("mov.b64 {%0,%1}, %2;" : "=f"(lo), "=f"(hi) : "l"(a));
    return lo + hi;
}
DEVINL ull pack2(float lo, float hi) {
    ull r;
    asm("mov.b64 %0, {%1,%2};" : "=l"(r) : "f"(lo), "f"(hi));
    return r;
}
DEVINL void upk(ull a, float& lo, float& hi) {
    asm("mov.b64 {%0,%1}, %2;" : "=f"(lo), "=f"(hi) : "l"(a));
}

DEVINL float sigm(float x) { return __fdividef(1.f, 1.f + __expf(-x)); }
DEVINL float tanh_(float x) { return __fdividef(2.f, 1.f + __expf(-2.f * x)) - 1.f; }

// ---------------------------------------------------------------------------
// smem layout (floats) — dynamic shared
//   conv1p weights: channel-PAIRS  [(3m+k)*64 + 2o]
//   conv1t / conv2 weights: channel-QUADS [(3mm+k)*128 + 4o]
//   prwT: quad-packed (w[o][2q], w[o+32][2q], w[o][2q+1], w[o+32][2q+1])
// ---------------------------------------------------------------------------
constexpr int OFF_W1P  = 0;                       // 576
constexpr int OFF_W1T  = OFF_W1P + 576;           // 1152
constexpr int OFF_W2P  = OFF_W1T + 1152;          // 3072
constexpr int OFF_W2T  = OFF_W2P + 3072;          // 3072
constexpr int OFF_B1P  = OFF_W2T + 3072;          // 32
constexpr int OFF_B1T  = OFF_B1P + 32;            // 32
constexpr int OFF_B2P  = OFF_B1T + 32;            // 32
constexpr int OFF_B2T  = OFF_B2P + 32;            // 32
constexpr int OFF_BIAS = OFF_B2T + 32;            // 256
constexpr int OFF_XP   = OFF_BIAS + 256;          // 8 * 128
constexpr int OFF_XT   = OFF_XP + 8 * 128;        // 8 * 256
constexpr int OFF_H1   = OFF_XT + 8 * 256;        // 8 * 576
constexpr int OFF_CAT  = OFF_H1 + 8 * 576;        // 8 * 80
constexpr int OFF_PRJ  = OFF_CAT + 8 * 80;        // 16 * 64
constexpr int OFF_PRW  = OFF_PRJ + 16 * 64;       // 36 * 128 = 4608
constexpr int SMEM_FLOATS = OFF_PRW + 4608;       // 22208
constexpr int SMEM_BYTES = SMEM_FLOATS * 4;       // 88832 B

// ---------------------------------------------------------------------------
// conv1 over channel PAIRS (pressure, stride 6). Full 18-output pass.
// ---------------------------------------------------------------------------
template <int NPAIR, int STRIDE>
DEVINL void conv1P(const float* __restrict__ s_x, const float* __restrict__ s_w,
                   float bv, float* __restrict__ h1T) {
    ull acc[18];
#pragma unroll
    for (int j = 0; j < 18; j++) acc[j] = 0ull;
#pragma unroll
    for (int m = 0; m < NPAIR; m++) {
        ull w0 = *reinterpret_cast<const ull*>(s_w + (3 * m + 0) * 64);
        ull w1 = *reinterpret_cast<const ull*>(s_w + (3 * m + 1) * 64);
        ull w2 = *reinterpret_cast<const ull*>(s_w + (3 * m + 2) * 64);
#pragma unroll
        for (int j = 0; j < 20; j++) {
            ull v = *reinterpret_cast<const ull*>(s_x + j * STRIDE + 2 * m);
            if (j < 18) fma2(acc[j], v, w0);
            if (j >= 1 && j <= 18) fma2(acc[j - 1], v, w1);
            if (j >= 2) fma2(acc[j - 2], v, w2);
        }
    }
#pragma unroll
    for (int j = 0; j < 18; j++)
        h1T[j * 32] = fmaxf(hsum2(acc[j]) + bv, 0.f);
}

// ---------------------------------------------------------------------------
// conv1 over channel QUADS (torque, stride 12). Full 18-output pass.
// ---------------------------------------------------------------------------
template <int NQUAD, int STRIDE>
DEVINL void conv1Q(const float* __restrict__ s_x, const float* __restrict__ s_w,
                   float bv, float* __restrict__ h1T) {
    ull acc[18];
#pragma unroll
    for (int j = 0; j < 18; j++) acc[j] = 0ull;
#pragma unroll
    for (int mm = 0; mm < NQUAD; mm++) {
        ulonglong2 w0 = *reinterpret_cast<const ulonglong2*>(s_w + (3 * mm + 0) * 128);
        ulonglong2 w1 = *reinterpret_cast<const ulonglong2*>(s_w + (3 * mm + 1) * 128);
        ulonglong2 w2 = *reinterpret_cast<const ulonglong2*>(s_w + (3 * mm + 2) * 128);
#pragma unroll
        for (int j = 0; j < 20; j++) {
            ulonglong2 v = *reinterpret_cast<const ulonglong2*>(s_x + j * STRIDE + 4 * mm);
            if (j < 18)            { fma2(acc[j], v.x, w0.x);     fma2(acc[j], v.y, w0.y); }
            if (j >= 1 && j <= 18) { fma2(acc[j - 1], v.x, w1.x); fma2(acc[j - 1], v.y, w1.y); }
            if (j >= 2)            { fma2(acc[j - 2], v.x, w2.x); fma2(acc[j - 2], v.y, w2.y); }
        }
    }
#pragma unroll
    for (int j = 0; j < 18; j++)
        h1T[j * 32] = fmaxf(hsum2(acc[j]) + bv, 0.f);
}

// ---------------------------------------------------------------------------
// conv2 over channel QUADS + relu + mean pool. Full 16-output pass.
// ---------------------------------------------------------------------------
DEVINL float conv2Q(const float* __restrict__ h1T, const float* __restrict__ s_w,
                    float bv) {
    ull acc[16];
#pragma unroll
    for (int j = 0; j < 16; j++) acc[j] = 0ull;
#pragma unroll 2
    for (int mm = 0; mm < 8; mm++) {
        ulonglong2 w0 = *reinterpret_cast<const ulonglong2*>(s_w + (3 * mm + 0) * 128);
        ulonglong2 w1 = *reinterpret_cast<const ulonglong2*>(s_w + (3 * mm + 1) * 128);
        ulonglong2 w2 = *reinterpret_cast<const ulonglong2*>(s_w + (3 * mm + 2) * 128);
#pragma unroll
        for (int j = 0; j < 18; j++) {
            ulonglong2 v = *reinterpret_cast<const ulonglong2*>(h1T + j * 32 + 4 * mm);
            if (j < 16)            { fma2(acc[j], v.x, w0.x);     fma2(acc[j], v.y, w0.y); }
            if (j >= 1 && j <= 16) { fma2(acc[j - 1], v.x, w1.x); fma2(acc[j - 1], v.y, w1.y); }
            if (j >= 2)            { fma2(acc[j - 2], v.x, w2.x); fma2(acc[j - 2], v.y, w2.y); }
        }
    }
    float s = 0.f;
#pragma unroll
    for (int j = 0; j < 16; j++)
        s += fmaxf(hsum2(acc[j]) + bv, 0.f);
    return s * (1.f / 16.f);
}

// ---------------------------------------------------------------------------
// Encoder kernel: warp = 2 windows (sequential).
// ---------------------------------------------------------------------------
__global__ void __launch_bounds__(256) enc_kernel(
    const float* __restrict__ pressure, const float* __restrict__ torque,
    const float* __restrict__ frag,
    const float* __restrict__ pw1, const float* __restrict__ pb1,
    const float* __restrict__ pw2, const float* __restrict__ pb2,
    const float* __restrict__ tw1, const float* __restrict__ tb1,
    const float* __restrict__ tw2, const float* __restrict__ tb2,
    const float* __restrict__ fw, const float* __restrict__ fb,
    const float* __restrict__ prw, const float* __restrict__ prb,
    const float* __restrict__ Wih, const float* __restrict__ bih,
    const float* __restrict__ bhh) {
    extern __shared__ float sm[];
    const int tid = threadIdx.x;
    const int lane = tid & 31;
    const int warp = tid >> 5;

    // ---- stage weights ----
    for (int t = tid; t < 32 * 3 * 3; t += 256) {         // conv1p pairs
        int o = t / 9, rem = t % 9, m = rem / 3, k = rem % 3;
        int di = OFF_W1P + (3 * m + k) * 64 + 2 * o;
        sm[di]     = pw1[(o * NP + 2 * m) * 3 + k];
        sm[di + 1] = pw1[(o * NP + 2 * m + 1) * 3 + k];
    }
    for (int t = tid; t < 32 * 3 * 3; t += 256) {         // conv1t quads
        int o = t / 9, rem = t % 9, mm = rem / 3, k = rem % 3;
        int di = OFF_W1T + (3 * mm + k) * 128 + 4 * o;
#pragma unroll
        for (int q = 0; q < 4; q++)
            sm[di + q] = tw1[(o * NT + 4 * mm + q) * 3 + k];
    }
    for (int t = tid; t < 32 * 8 * 3; t += 256) {         // conv2 quads
        int o = t / 24, rem = t % 24, mm = rem / 3, k = rem % 3;
        int di = (3 * mm + k) * 128 + 4 * o;
#pragma unroll
        for (int q = 0; q < 4; q++) {
            int si = (o * CC + 4 * mm + q) * 3 + k;
            sm[OFF_W2P + di + q] = pw2[si];
            sm[OFF_W2T + di + q] = tw2[si];
        }
    }
    // prwT quad-pack: [q*128 + 4o] = (w[o][2q], w[o+32][2q], w[o][2q+1], w[o+32][2q+1])
    for (int t = tid; t < 36 * 32; t += 256) {
        int q = t >> 5, o = t & 31;
        int di = OFF_PRW + q * 128 + o * 4;
        sm[di + 0] = prw[o * 72 + 2 * q];
        sm[di + 1] = prw[(o + 32) * 72 + 2 * q];
        sm[di + 2] = prw[o * 72 + 2 * q + 1];
        sm[di + 3] = prw[(o + 32) * 72 + 2 * q + 1];
    }
    if (tid < 32) {
        sm[OFF_B1P + tid] = pb1[tid]; sm[OFF_B1T + tid] = tb1[tid];
        sm[OFF_B2P + tid] = pb2[tid]; sm[OFF_B2T + tid] = tb2[tid];
    }
    sm[OFF_BIAS + tid] = bih[tid] + bhh[tid];
    __syncthreads();

    const int wbase = blockIdx.x * WPB;

    float* sxp = sm + OFF_XP + warp * 128;
    float* sxt = sm + OFF_XT + warp * 256;
    float* sh1 = sm + OFF_H1 + warp * 576;
    float* sft = sm + OFF_CAT + warp * 80;

#pragma unroll 1
    for (int w2 = 0; w2 < 2; w2++) {
        const int win = warp * 2 + w2;
        const int wi = wbase + win;
        const int b = wi >> 8;
        float* spj = sm + OFF_PRJ + win * 64;

        // ---- load window inputs (raw [pos][ch] layout kept) ----
        {
            const float4* gp4 = reinterpret_cast<const float4*>(pressure + wi * 120);
            if (lane < 30) reinterpret_cast<float4*>(sxp)[lane] = gp4[lane];
            const float4* gt4 = reinterpret_cast<const float4*>(torque + wi * 240);
            reinterpret_cast<float4*>(sxt)[lane] = gt4[lane];
            if (lane < 28) reinterpret_cast<float4*>(sxt)[lane + 32] = gt4[lane + 32];
        }
        __syncwarp();

        // ---- pressure: conv1 -> h1T -> conv2 -> pooled ----
        conv1P<3, NP>(sxp, sm + OFF_W1P + 2 * lane, sm[OFF_B1P + lane], sh1 + lane);
        __syncwarp();
        float poolp = conv2Q(sh1, sm + OFF_W2P + 4 * lane, sm[OFF_B2P + lane]);
        __syncwarp();

        // ---- torque: conv1 -> h1T -> conv2 -> pooled ----
        conv1Q<3, NT>(sxt, sm + OFF_W1T + 4 * lane, sm[OFF_B1T + lane], sh1 + lane);
        __syncwarp();
        float poolt = conv2Q(sh1, sm + OFF_W2T + 4 * lane, sm[OFF_B2T + lane]);

        sft[lane] = poolp;
        sft[32 + lane] = poolt;
        if (lane < FD) sft[64 + lane] = fmaxf(fmaf(frag[b], fw[lane], fb[lane]), 0.f);
        __syncwarp();

        // ---- projection: packed (o, o+32) outputs from smem prwT ----
        {
            ull acc = 0ull, accb = 0ull;
            const float* sw = sm + OFF_PRW + 4 * lane;
#pragma unroll
            for (int q = 0; q < 36; q++) {
                ulonglong2 wq = *reinterpret_cast<const ulonglong2*>(sw + q * 128);
                ull xp = *reinterpret_cast<const ull*>(sft + 2 * q);
                float x0, x1; upk(xp, x0, x1);
                fma2(acc,  wq.x, pack2(x0, x0));
                fma2(accb, wq.y, pack2(x1, x1));
            }
            add2(acc, acc, accb);
            float lo, hi; upk(acc, lo, hi);
            spj[lane]      = fmaxf(lo + prb[lane], 0.f);
            spj[lane + 32] = fmaxf(hi + prb[lane + 32], 0.f);
        }
        __syncwarp();
    }
    __syncthreads();

    // ---- xg: gate tid for all 16 windows; Wih row held in registers ----
    {
        ull wv[32];
        const ulonglong2* wr = reinterpret_cast<const ulonglong2*>(Wih + tid * PROJ);
#pragma unroll
        for (int q = 0; q < 16; q++) {
            ulonglong2 v = wr[q];
            wv[2 * q] = v.x; wv[2 * q + 1] = v.y;
        }
        float bias = sm[OFF_BIAS + tid];
#pragma unroll 2
        for (int win = 0; win < WPB; win++) {
            const ulonglong2* fr = reinterpret_cast<const ulonglong2*>(sm + OFF_PRJ + win * 64);
            ull a0 = pack2(bias, 0.f), a1 = 0ull, a2 = 0ull, a3 = 0ull;
#pragma unroll
            for (int q = 0; q < 16; q++) {
                ulonglong2 fv = fr[q];
                if ((q & 1) == 0) { fma2(a0, wv[2 * q], fv.x); fma2(a1, wv[2 * q + 1], fv.y); }
                else              { fma2(a2, wv[2 * q], fv.x); fma2(a3, wv[2 * q + 1], fv.y); }
            }
            add2(a0, a0, a2);
            add2(a1, a1, a3);
            add2(a0, a0, a1);
            g_xg[(wbase + win) * NG + tid] = hsum2(a0);
        }
    }
}

// ---------------------------------------------------------------------------
// LSTM kernel: one block per batch row, 512 threads = 2 per gate.
// Half-dots combined with one shfl_xor; activation pre-barrier; smem exchange.
// ---------------------------------------------------------------------------
__global__ void __launch_bounds__(512) lstm_kernel(
    const float* __restrict__ Whh, float* __restrict__ out) {
    __shared__ __align__(16) float s_h[PROJ];
    __shared__ float s_gact[NG];

    const int tid = threadIdx.x;
    const int gate = tid >> 1;       // 0..255
    const int half = tid & 1;        // which 32-wide half of the dot
    const int cls = gate >> 6;       // 0:i 1:f 2:g 3:o
    const int b = blockIdx.x;

    ull wreg[16];
    {
        const ulonglong2* w2 = reinterpret_cast<const ulonglong2*>(Whh + gate * PROJ + half * 32);
#pragma unroll
        for (int q = 0; q < 8; q++) {
            ulonglong2 v = w2[q];
            wreg[2 * q] = v.x;
            wreg[2 * q + 1] = v.y;
        }
    }

    if (tid < PROJ) s_h[tid] = 0.f;
    float c = 0.f;

    const float* xg = g_xg + b * T * NG;
    float* hs = g_hs + b * T * PROJ;
    float xnext = xg[gate];
    __syncthreads();

    for (int t = 0; t < T; t++) {
        float xcur = xnext;
        int tn = (t + 1 < T) ? (t + 1) : (T - 1);
        xnext = xg[tn * NG + gate];

        // half matvec: 16 fma2, 4 chains
        ull a0 = half ? 0ull : pack2(xcur, 0.f);
        ull a1 = 0ull, a2 = 0ull, a3 = 0ull;
        const ulonglong2* h2 = reinterpret_cast<const ulonglong2*>(s_h + half * 32);
#pragma unroll
        for (int q = 0; q < 8; q++) {
            ulonglong2 hv = h2[q];
            if ((q & 1) == 0) { fma2(a0, wreg[2 * q], hv.x); fma2(a1, wreg[2 * q + 1], hv.y); }
            else              { fma2(a2, wreg[2 * q], hv.x); fma2(a3, wreg[2 * q + 1], hv.y); }
        }
        add2(a0, a0, a2);
        add2(a1, a1, a3);
        add2(a0, a0, a1);
        float g = hsum2(a0);
        g += __shfl_xor_sync(0xffffffffu, g, 1);      // combine halves

        float act = (cls == 2) ? tanh_(g) : sigm(g);
        if (half == 0) s_gact[gate] = act;
        __syncthreads();

        if (tid < PROJ) {
            float ai = s_gact[tid];
            float af = s_gact[PROJ + tid];
            float ag = s_gact[2 * PROJ + tid];
            float ao = s_gact[3 * PROJ + tid];
            c = fmaf(af, c, ai * ag);
            float h = ao * tanh_(c);
            s_h[tid] = h;
            hs[t * PROJ + tid] = h;
        }
        __syncthreads();
    }

    if (tid < PROJ) {
        out[B * T * 4 + b * PROJ + tid] = s_h[tid];             // hT
        out[B * T * 4 + B * PROJ + b * PROJ + tid] = c;         // cT
    }
}

// ---------------------------------------------------------------------------
// Head kernel: out[wi, m] = sigmoid(h[wi] . hw[m] + hb[m]), fully parallel.
// ---------------------------------------------------------------------------
__global__ void __launch_bounds__(256) head_kernel(
    const float* __restrict__ hw, const float* __restrict__ hb,
    float* __restrict__ out) {
    __shared__ __align__(16) float s_hw[4 * PROJ];
    __shared__ float s_hb[4];
    const int tid = threadIdx.x;
    s_hw[tid] = hw[tid];
    if (tid < 4) s_hb[tid] = hb[tid];
    __syncthreads();

    const int gid = blockIdx.x * 256 + tid;
    const int wi = gid >> 2, m = gid & 3;
    const float4* hr = reinterpret_cast<const float4*>(g_hs + wi * PROJ);
    const float4* wr = reinterpret_cast<const float4*>(s_hw) + m * 16;
    float a0 = s_hb[m], a1 = 0.f;
#pragma unroll
    for (int q = 0; q < 16; q += 2) {
        float4 h0 = hr[q], w0 = wr[q];
        float4 h1 = hr[q + 1], w1 = wr[q + 1];
        a0 = fmaf(h0.x, w0.x, a0); a0 = fmaf(h0.y, w0.y, a0);
        a0 = fmaf(h0.z, w0.z, a0); a0 = fmaf(h0.w, w0.w, a0);
        a1 = fmaf(h1.x, w1.x, a1); a1 = fmaf(h1.y, w1.y, a1);
        a1 = fmaf(h1.z, w1.z, a1); a1 = fmaf(h1.w, w1.w, a1);
    }
    out[gid] = sigm(a0 + a1);
}

// ---------------------------------------------------------------------------
extern "C" void kernel_launch(void* const* d_in, const int* in_sizes, int n_in,
                              void* d_out, int out_size) {
    const float* pressure = (const float*)d_in[0];
    const float* torque   = (const float*)d_in[1];
    const float* frag     = (const float*)d_in[2];
    const float* pw1 = (const float*)d_in[3];
    const float* pb1 = (const float*)d_in[4];
    const float* pw2 = (const float*)d_in[5];
    const float* pb2 = (const float*)d_in[6];
    const float* tw1 = (const float*)d_in[7];
    const float* tb1 = (const float*)d_in[8];
    const float* tw2 = (const float*)d_in[9];
    const float* tb2 = (const float*)d_in[10];
    const float* fw  = (const float*)d_in[11];
    const float* fb  = (const float*)d_in[12];
    const float* prw = (const float*)d_in[13];
    const float* prb = (const float*)d_in[14];
    const float* Wih = (const float*)d_in[15];
    const float* Whh = (const float*)d_in[16];
    const float* bih = (const float*)d_in[17];
    const float* bhh = (const float*)d_in[18];
    const float* hw  = (const float*)d_in[19];
    const float* hb  = (const float*)d_in[20];

    static bool attr_set = false;
    if (!attr_set) {
        cudaFuncSetAttribute(enc_kernel, cudaFuncAttributeMaxDynamicSharedMemorySize,
                             SMEM_BYTES);
        attr_set = true;
    }

    enc_kernel<<<NWIN / WPB, 256, SMEM_BYTES>>>(pressure, torque, frag,
                                                pw1, pb1, pw2, pb2, tw1, tb1, tw2, tb2,
                                                fw, fb, prw, prb, Wih, bih, bhh);
    lstm_kernel<<<B, 512>>>(Whh, (float*)d_out);
    head_kernel<<<(B * T * 4) / 256, 256>>>(hw, hb, (float*)d_out);
}

// round 10
// speedup vs baseline: 1.5150x; 1.3473x over previous
#include <cuda_runtime.h>

#define DEVINL __device__ __forceinline__
typedef unsigned long long ull;

constexpr int B = 64, T = 256, W = 20, NP = 6, NT = 12, CC = 32, FD = 8, PROJ = 64;
constexpr int NG = 4 * PROJ;            // 256 gates
constexpr int NWIN = B * T;             // 16384
constexpr int WPB = 16;                 // windows per enc block (2 per warp)
constexpr int NCHUNK = 16;              // t-chunks per batch row

// scratch
__device__ float g_xg[NWIN * NG];       // 16 MB: xg = feat @ Wih^T + (bih+bhh)
__device__ float g_hs[NWIN * PROJ];     // 4 MB: per-step hidden states
__device__ int   g_flag[B * NCHUNK];    // producer->consumer chunk flags

DEVINL void fma2(ull& d, ull a, ull b) {
    asm("fma.rn.f32x2 %0, %1, %2, %0;" : "+l"(d) : "l"(a), "l"(b));
}
DEVINL void add2(ull& d, ull a, ull b) {
    asm("add.rn.f32x2 %0, %1, %2;" : "=l"(d) : "l"(a), "l"(b));
}
DEVINL float hsum2(ull a) {
    float lo, hi;
    asm("mov.b64 {%0,%1}, %2;" : "=f"(lo), "=f"(hi) : "l"(a));
    return lo + hi;
}
DEVINL ull pack2(float lo, float hi) {
    ull r;
    asm("mov.b64 %0, {%1,%2};" : "=l"(r) : "f"(lo), "f"(hi));
    return r;
}
DEVINL void upk(ull a, float& lo, float& hi) {
    asm("mov.b64 {%0,%1}, %2;" : "=f"(lo), "=f"(hi) : "l"(a));
}

DEVINL float sigm(float x) { return __fdividef(1.f, 1.f + __expf(-x)); }
DEVINL float tanh_(float x) { return __fdividef(2.f, 1.f + __expf(-2.f * x)) - 1.f; }

// ---------------------------------------------------------------------------
// smem layout (floats) — dynamic shared (enc role only)
// ---------------------------------------------------------------------------
constexpr int OFF_W1P  = 0;                       // 576
constexpr int OFF_W1T  = OFF_W1P + 576;           // 1152
constexpr int OFF_W2P  = OFF_W1T + 1152;          // 3072
constexpr int OFF_W2T  = OFF_W2P + 3072;          // 3072
constexpr int OFF_B1P  = OFF_W2T + 3072;          // 32
constexpr int OFF_B1T  = OFF_B1P + 32;            // 32
constexpr int OFF_B2P  = OFF_B1T + 32;            // 32
constexpr int OFF_B2T  = OFF_B2P + 32;            // 32
constexpr int OFF_BIAS = OFF_B2T + 32;            // 256
constexpr int OFF_XP   = OFF_BIAS + 256;          // 8 * 128
constexpr int OFF_XT   = OFF_XP + 8 * 128;        // 8 * 256
constexpr int OFF_H1   = OFF_XT + 8 * 256;        // 8 * 576
constexpr int OFF_CAT  = OFF_H1 + 8 * 576;        // 8 * 80
constexpr int OFF_PRJ  = OFF_CAT + 8 * 80;        // 16 * 64
constexpr int OFF_PRW  = OFF_PRJ + 16 * 64;       // 4608
constexpr int SMEM_FLOATS = OFF_PRW + 4608;
constexpr int SMEM_BYTES = SMEM_FLOATS * 4;       // 88832 B

// ---------------------------------------------------------------------------
// conv helpers (r9, unchanged)
// ---------------------------------------------------------------------------
template <int NPAIR, int STRIDE>
DEVINL void conv1P(const float* __restrict__ s_x, const float* __restrict__ s_w,
                   float bv, float* __restrict__ h1T) {
    ull acc[18];
#pragma unroll
    for (int j = 0; j < 18; j++) acc[j] = 0ull;
#pragma unroll
    for (int m = 0; m < NPAIR; m++) {
        ull w0 = *reinterpret_cast<const ull*>(s_w + (3 * m + 0) * 64);
        ull w1 = *reinterpret_cast<const ull*>(s_w + (3 * m + 1) * 64);
        ull w2 = *reinterpret_cast<const ull*>(s_w + (3 * m + 2) * 64);
#pragma unroll
        for (int j = 0; j < 20; j++) {
            ull v = *reinterpret_cast<const ull*>(s_x + j * STRIDE + 2 * m);
            if (j < 18) fma2(acc[j], v, w0);
            if (j >= 1 && j <= 18) fma2(acc[j - 1], v, w1);
            if (j >= 2) fma2(acc[j - 2], v, w2);
        }
    }
#pragma unroll
    for (int j = 0; j < 18; j++)
        h1T[j * 32] = fmaxf(hsum2(acc[j]) + bv, 0.f);
}

template <int NQUAD, int STRIDE>
DEVINL void conv1Q(const float* __restrict__ s_x, const float* __restrict__ s_w,
                   float bv, float* __restrict__ h1T) {
    ull acc[18];
#pragma unroll
    for (int j = 0; j < 18; j++) acc[j] = 0ull;
#pragma unroll
    for (int mm = 0; mm < NQUAD; mm++) {
        ulonglong2 w0 = *reinterpret_cast<const ulonglong2*>(s_w + (3 * mm + 0) * 128);
        ulonglong2 w1 = *reinterpret_cast<const ulonglong2*>(s_w + (3 * mm + 1) * 128);
        ulonglong2 w2 = *reinterpret_cast<const ulonglong2*>(s_w + (3 * mm + 2) * 128);
#pragma unroll
        for (int j = 0; j < 20; j++) {
            ulonglong2 v = *reinterpret_cast<const ulonglong2*>(s_x + j * STRIDE + 4 * mm);
            if (j < 18)            { fma2(acc[j], v.x, w0.x);     fma2(acc[j], v.y, w0.y); }
            if (j >= 1 && j <= 18) { fma2(acc[j - 1], v.x, w1.x); fma2(acc[j - 1], v.y, w1.y); }
            if (j >= 2)            { fma2(acc[j - 2], v.x, w2.x); fma2(acc[j - 2], v.y, w2.y); }
        }
    }
#pragma unroll
    for (int j = 0; j < 18; j++)
        h1T[j * 32] = fmaxf(hsum2(acc[j]) + bv, 0.f);
}

DEVINL float conv2Q(const float* __restrict__ h1T, const float* __restrict__ s_w,
                    float bv) {
    ull acc[16];
#pragma unroll
    for (int j = 0; j < 16; j++) acc[j] = 0ull;
#pragma unroll 2
    for (int mm = 0; mm < 8; mm++) {
        ulonglong2 w0 = *reinterpret_cast<const ulonglong2*>(s_w + (3 * mm + 0) * 128);
        ulonglong2 w1 = *reinterpret_cast<const ulonglong2*>(s_w + (3 * mm + 1) * 128);
        ulonglong2 w2 = *reinterpret_cast<const ulonglong2*>(s_w + (3 * mm + 2) * 128);
#pragma unroll
        for (int j = 0; j < 18; j++) {
            ulonglong2 v = *reinterpret_cast<const ulonglong2*>(h1T + j * 32 + 4 * mm);
            if (j < 16)            { fma2(acc[j], v.x, w0.x);     fma2(acc[j], v.y, w0.y); }
            if (j >= 1 && j <= 16) { fma2(acc[j - 1], v.x, w1.x); fma2(acc[j - 1], v.y, w1.y); }
            if (j >= 2)            { fma2(acc[j - 2], v.x, w2.x); fma2(acc[j - 2], v.y, w2.y); }
        }
    }
    float s = 0.f;
#pragma unroll
    for (int j = 0; j < 16; j++)
        s += fmaxf(hsum2(acc[j]) + bv, 0.f);
    return s * (1.f / 16.f);
}

// ---------------------------------------------------------------------------
// Fused kernel. Blocks 0..63: LSTM role (b = blockIdx). Blocks 64..1087: enc
// role producing (b = k&63, tc = k>>6) and raising g_flag[b*16+tc].
// ---------------------------------------------------------------------------
__global__ void __launch_bounds__(256) fused_kernel(
    const float* __restrict__ pressure, const float* __restrict__ torque,
    const float* __restrict__ frag,
    const float* __restrict__ pw1, const float* __restrict__ pb1,
    const float* __restrict__ pw2, const float* __restrict__ pb2,
    const float* __restrict__ tw1, const float* __restrict__ tb1,
    const float* __restrict__ tw2, const float* __restrict__ tb2,
    const float* __restrict__ fw, const float* __restrict__ fb,
    const float* __restrict__ prw, const float* __restrict__ prb,
    const float* __restrict__ Wih, const float* __restrict__ bih,
    const float* __restrict__ bhh, const float* __restrict__ Whh,
    float* __restrict__ out) {
    extern __shared__ float sm[];
    const int tid = threadIdx.x;

    if (blockIdx.x < 64) {
        // =================== LSTM role (r8 design, chunked) ===================
        __shared__ __align__(16) float s_h[PROJ];
        __shared__ float s_gact[NG];

        const int b = blockIdx.x;
        const int cls = tid >> 6;  // 0:i 1:f 2:g 3:o

        ull wreg[PROJ / 2];
        {
            const ulonglong2* w2 = reinterpret_cast<const ulonglong2*>(Whh + tid * PROJ);
#pragma unroll
            for (int q = 0; q < PROJ / 4; q++) {
                ulonglong2 v = w2[q];
                wreg[2 * q] = v.x;
                wreg[2 * q + 1] = v.y;
            }
        }

        if (tid < PROJ) s_h[tid] = 0.f;
        float c = 0.f;

        const float* xg = g_xg + b * T * NG;
        float* hs = g_hs + b * T * PROJ;
        __syncthreads();

        for (int ch = 0; ch < NCHUNK; ch++) {
            // wait for producer of chunk ch
            if (tid == 0) {
                while (atomicAdd(&g_flag[b * NCHUNK + ch], 0) == 0) { }
            }
            __syncthreads();

            float xnext = xg[(ch * 16) * NG + tid];
#pragma unroll 1
            for (int tt = 0; tt < 16; tt++) {
                const int t = ch * 16 + tt;
                float xcur = xnext;
                if (tt < 15) xnext = xg[(t + 1) * NG + tid];  // stays inside chunk

                // 8 accumulator chains (depth 4), then 3-level reduction
                ull a[8];
                a[0] = pack2(xcur, 0.f);
#pragma unroll
                for (int i = 1; i < 8; i++) a[i] = 0ull;
                const ulonglong2* h2 = reinterpret_cast<const ulonglong2*>(s_h);
#pragma unroll
                for (int q = 0; q < 16; q++) {
                    ulonglong2 hv = h2[q];
                    fma2(a[(2 * q) & 7], wreg[2 * q], hv.x);
                    fma2(a[(2 * q + 1) & 7], wreg[2 * q + 1], hv.y);
                }
                add2(a[0], a[0], a[4]);
                add2(a[1], a[1], a[5]);
                add2(a[2], a[2], a[6]);
                add2(a[3], a[3], a[7]);
                add2(a[0], a[0], a[2]);
                add2(a[1], a[1], a[3]);
                add2(a[0], a[0], a[1]);
                float g = hsum2(a[0]);
                s_gact[tid] = (cls == 2) ? tanh_(g) : sigm(g);
                __syncthreads();

                if (tid < PROJ) {
                    float ai = s_gact[tid];
                    float af = s_gact[PROJ + tid];
                    float ag = s_gact[2 * PROJ + tid];
                    float ao = s_gact[3 * PROJ + tid];
                    c = fmaf(af, c, ai * ag);
                    float h = ao * tanh_(c);
                    s_h[tid] = h;
                    hs[t * PROJ + tid] = h;
                }
                __syncthreads();
            }
        }

        if (tid < PROJ) {
            out[B * T * 4 + b * PROJ + tid] = s_h[tid];             // hT
            out[B * T * 4 + B * PROJ + b * PROJ + tid] = c;         // cT
        }
        return;
    }

    // ======================= Encoder role (r9 design) =======================
    const int k = blockIdx.x - 64;
    const int b = k & 63;
    const int tc = k >> 6;
    const int lane = tid & 31;
    const int warp = tid >> 5;

    // ---- stage weights ----
    for (int t = tid; t < 32 * 3 * 3; t += 256) {         // conv1p pairs
        int o = t / 9, rem = t % 9, m = rem / 3, kk = rem % 3;
        int di = OFF_W1P + (3 * m + kk) * 64 + 2 * o;
        sm[di]     = pw1[(o * NP + 2 * m) * 3 + kk];
        sm[di + 1] = pw1[(o * NP + 2 * m + 1) * 3 + kk];
    }
    for (int t = tid; t < 32 * 3 * 3; t += 256) {         // conv1t quads
        int o = t / 9, rem = t % 9, mm = rem / 3, kk = rem % 3;
        int di = OFF_W1T + (3 * mm + kk) * 128 + 4 * o;
#pragma unroll
        for (int q = 0; q < 4; q++)
            sm[di + q] = tw1[(o * NT + 4 * mm + q) * 3 + kk];
    }
    for (int t = tid; t < 32 * 8 * 3; t += 256) {         // conv2 quads
        int o = t / 24, rem = t % 24, mm = rem / 3, kk = rem % 3;
        int di = (3 * mm + kk) * 128 + 4 * o;
#pragma unroll
        for (int q = 0; q < 4; q++) {
            int si = (o * CC + 4 * mm + q) * 3 + kk;
            sm[OFF_W2P + di + q] = pw2[si];
            sm[OFF_W2T + di + q] = tw2[si];
        }
    }
    for (int t = tid; t < 36 * 32; t += 256) {            // prwT quad-pack
        int q = t >> 5, o = t & 31;
        int di = OFF_PRW + q * 128 + o * 4;
        sm[di + 0] = prw[o * 72 + 2 * q];
        sm[di + 1] = prw[(o + 32) * 72 + 2 * q];
        sm[di + 2] = prw[o * 72 + 2 * q + 1];
        sm[di + 3] = prw[(o + 32) * 72 + 2 * q + 1];
    }
    if (tid < 32) {
        sm[OFF_B1P + tid] = pb1[tid]; sm[OFF_B1T + tid] = tb1[tid];
        sm[OFF_B2P + tid] = pb2[tid]; sm[OFF_B2T + tid] = tb2[tid];
    }
    sm[OFF_BIAS + tid] = bih[tid] + bhh[tid];
    __syncthreads();

    const int wbase = b * 256 + tc * 16;   // wi = wbase + win, win = 0..15

    float* sxp = sm + OFF_XP + warp * 128;
    float* sxt = sm + OFF_XT + warp * 256;
    float* sh1 = sm + OFF_H1 + warp * 576;
    float* sft = sm + OFF_CAT + warp * 80;

#pragma unroll 1
    for (int w2 = 0; w2 < 2; w2++) {
        const int win = warp * 2 + w2;
        const int wi = wbase + win;
        float* spj = sm + OFF_PRJ + win * 64;

        // ---- load window inputs (raw [pos][ch] layout kept) ----
        {
            const float4* gp4 = reinterpret_cast<const float4*>(pressure + wi * 120);
            if (lane < 30) reinterpret_cast<float4*>(sxp)[lane] = gp4[lane];
            const float4* gt4 = reinterpret_cast<const float4*>(torque + wi * 240);
            reinterpret_cast<float4*>(sxt)[lane] = gt4[lane];
            if (lane < 28) reinterpret_cast<float4*>(sxt)[lane + 32] = gt4[lane + 32];
        }
        __syncwarp();

        // ---- pressure: conv1 -> h1T -> conv2 -> pooled ----
        conv1P<3, NP>(sxp, sm + OFF_W1P + 2 * lane, sm[OFF_B1P + lane], sh1 + lane);
        __syncwarp();
        float poolp = conv2Q(sh1, sm + OFF_W2P + 4 * lane, sm[OFF_B2P + lane]);
        __syncwarp();

        // ---- torque: conv1 -> h1T -> conv2 -> pooled ----
        conv1Q<3, NT>(sxt, sm + OFF_W1T + 4 * lane, sm[OFF_B1T + lane], sh1 + lane);
        __syncwarp();
        float poolt = conv2Q(sh1, sm + OFF_W2T + 4 * lane, sm[OFF_B2T + lane]);

        sft[lane] = poolp;
        sft[32 + lane] = poolt;
        if (lane < FD) sft[64 + lane] = fmaxf(fmaf(frag[b], fw[lane], fb[lane]), 0.f);
        __syncwarp();

        // ---- projection: packed (o, o+32) outputs from smem prwT ----
        {
            ull acc = 0ull, accb = 0ull;
            const float* sw = sm + OFF_PRW + 4 * lane;
#pragma unroll
            for (int q = 0; q < 36; q++) {
                ulonglong2 wq = *reinterpret_cast<const ulonglong2*>(sw + q * 128);
                ull xp = *reinterpret_cast<const ull*>(sft + 2 * q);
                float x0, x1; upk(xp, x0, x1);
                fma2(acc,  wq.x, pack2(x0, x0));
                fma2(accb, wq.y, pack2(x1, x1));
            }
            add2(acc, acc, accb);
            float lo, hi; upk(acc, lo, hi);
            spj[lane]      = fmaxf(lo + prb[lane], 0.f);
            spj[lane + 32] = fmaxf(hi + prb[lane + 32], 0.f);
        }
        __syncwarp();
    }
    __syncthreads();

    // ---- xg: gate tid for all 16 windows; Wih row held in registers ----
    {
        ull wv[32];
        const ulonglong2* wr = reinterpret_cast<const ulonglong2*>(Wih + tid * PROJ);
#pragma unroll
        for (int q = 0; q < 16; q++) {
            ulonglong2 v = wr[q];
            wv[2 * q] = v.x; wv[2 * q + 1] = v.y;
        }
        float bias = sm[OFF_BIAS + tid];
#pragma unroll 2
        for (int win = 0; win < WPB; win++) {
            const ulonglong2* fr = reinterpret_cast<const ulonglong2*>(sm + OFF_PRJ + win * 64);
            ull a0 = pack2(bias, 0.f), a1 = 0ull, a2 = 0ull, a3 = 0ull;
#pragma unroll
            for (int q = 0; q < 16; q++) {
                ulonglong2 fv = fr[q];
                if ((q & 1) == 0) { fma2(a0, wv[2 * q], fv.x); fma2(a1, wv[2 * q + 1], fv.y); }
                else              { fma2(a2, wv[2 * q], fv.x); fma2(a3, wv[2 * q + 1], fv.y); }
            }
            add2(a0, a0, a2);
            add2(a1, a1, a3);
            add2(a0, a0, a1);
            g_xg[(wbase + win) * NG + tid] = hsum2(a0);
        }
    }

    // ---- publish chunk ----
    __syncthreads();
    if (tid == 0) {
        __threadfence();
        atomicExch(&g_flag[b * NCHUNK + tc], 1);
    }
}

// ---------------------------------------------------------------------------
// Head kernel: out[wi, m] = sigmoid(h[wi] . hw[m] + hb[m]), fully parallel.
// ---------------------------------------------------------------------------
__global__ void __launch_bounds__(256) head_kernel(
    const float* __restrict__ hw, const float* __restrict__ hb,
    float* __restrict__ out) {
    __shared__ __align__(16) float s_hw[4 * PROJ];
    __shared__ float s_hb[4];
    const int tid = threadIdx.x;
    s_hw[tid] = hw[tid];
    if (tid < 4) s_hb[tid] = hb[tid];
    __syncthreads();

    const int gid = blockIdx.x * 256 + tid;
    const int wi = gid >> 2, m = gid & 3;
    const float4* hr = reinterpret_cast<const float4*>(g_hs + wi * PROJ);
    const float4* wr = reinterpret_cast<const float4*>(s_hw) + m * 16;
    float a0 = s_hb[m], a1 = 0.f;
#pragma unroll
    for (int q = 0; q < 16; q += 2) {
        float4 h0 = hr[q], w0 = wr[q];
        float4 h1 = hr[q + 1], w1 = wr[q + 1];
        a0 = fmaf(h0.x, w0.x, a0); a0 = fmaf(h0.y, w0.y, a0);
        a0 = fmaf(h0.z, w0.z, a0); a0 = fmaf(h0.w, w0.w, a0);
        a1 = fmaf(h1.x, w1.x, a1); a1 = fmaf(h1.y, w1.y, a1);
        a1 = fmaf(h1.z, w1.z, a1); a1 = fmaf(h1.w, w1.w, a1);
    }
    out[gid] = sigm(a0 + a1);
}

// ---------------------------------------------------------------------------
extern "C" void kernel_launch(void* const* d_in, const int* in_sizes, int n_in,
                              void* d_out, int out_size) {
    const float* pressure = (const float*)d_in[0];
    const float* torque   = (const float*)d_in[1];
    const float* frag     = (const float*)d_in[2];
    const float* pw1 = (const float*)d_in[3];
    const float* pb1 = (const float*)d_in[4];
    const float* pw2 = (const float*)d_in[5];
    const float* pb2 = (const float*)d_in[6];
    const float* tw1 = (const float*)d_in[7];
    const float* tb1 = (const float*)d_in[8];
    const float* tw2 = (const float*)d_in[9];
    const float* tb2 = (const float*)d_in[10];
    const float* fw  = (const float*)d_in[11];
    const float* fb  = (const float*)d_in[12];
    const float* prw = (const float*)d_in[13];
    const float* prb = (const float*)d_in[14];
    const float* Wih = (const float*)d_in[15];
    const float* Whh = (const float*)d_in[16];
    const float* bih = (const float*)d_in[17];
    const float* bhh = (const float*)d_in[18];
    const float* hw  = (const float*)d_in[19];
    const float* hb  = (const float*)d_in[20];

    static void* flags_ptr = nullptr;
    if (!flags_ptr) {
        cudaFuncSetAttribute(fused_kernel, cudaFuncAttributeMaxDynamicSharedMemorySize,
                             SMEM_BYTES);
        cudaGetSymbolAddress(&flags_ptr, g_flag);
    }

    cudaMemsetAsync(flags_ptr, 0, B * NCHUNK * sizeof(int));

    fused_kernel<<<64 + NWIN / WPB, 256, SMEM_BYTES>>>(
        pressure, torque, frag,
        pw1, pb1, pw2, pb2, tw1, tb1, tw2, tb2,
        fw, fb, prw, prb, Wih, bih, bhh, Whh, (float*)d_out);
    head_kernel<<<(B * T * 4) / 256, 256>>>(hw, hb, (float*)d_out);
}